// round 4
// baseline (speedup 1.0000x reference)
#include <cuda_runtime.h>
#include <cuda_bf16.h>

// Problem constants
#define T_TYPES 27
#define N_NODES 16384
#define B_BATCH 256
#define IN_DIM  300
#define HID     128
#define OUT_DIM 64

// Scratch for pooled means [T, B, IN_DIM]
__device__ __align__(16) float g_pooled[T_TYPES * B_BATCH * IN_DIM];

typedef unsigned long long ull;

__device__ __forceinline__ ull fma2(ull a, ull b, ull c) {
    ull d;
    asm("fma.rn.f32x2 %0, %1, %2, %3;" : "=l"(d) : "l"(a), "l"(b), "l"(c));
    return d;
}
__device__ __forceinline__ ull pack2(float x) {
    ull d; asm("mov.b64 %0, {%1, %1};" : "=l"(d) : "f"(x)); return d;
}
__device__ __forceinline__ void unpack2(ull v, float& lo, float& hi) {
    asm("mov.b64 {%0, %1}, %2;" : "=f"(lo), "=f"(hi) : "l"(v));
}

__device__ __forceinline__ int lower_bound_i32(const int* s, int n, int v) {
    int lo = 0, hi = n;
    while (lo < hi) {
        int mid = (lo + hi) >> 1;
        if (s[mid] < v) lo = mid + 1; else hi = mid;
    }
    return lo;
}

// ---------------------------------------------------------------------------
// Kernel 1: segment mean pooling. grid=(B,T), block=64.  (at HBM roofline)
// ---------------------------------------------------------------------------
__global__ void pool_kernel(const float* __restrict__ feat,
                            const int* __restrict__ seg) {
    const int b = blockIdx.x;
    const int t = blockIdx.y;
    const int tid = threadIdx.x;

    const int* s = seg + (size_t)t * N_NODES;
    __shared__ int s_bounds[2];
    if (tid < 2) s_bounds[tid] = lower_bound_i32(s, N_NODES, b + tid);
    __syncthreads();

    const int lo = s_bounds[0];
    const int cnt = s_bounds[1] - lo;

    float4 aA = make_float4(0.f, 0.f, 0.f, 0.f);
    float4 aB = make_float4(0.f, 0.f, 0.f, 0.f);
    const bool hasB = tid < 11;

    const float4* fb = (const float4*)(feat + ((size_t)t * N_NODES + lo) * IN_DIM);
    #pragma unroll 4
    for (int r = 0; r < cnt; ++r) {
        float4 v = __ldcs(&fb[tid]);
        aA.x += v.x; aA.y += v.y; aA.z += v.z; aA.w += v.w;
        if (hasB) {
            float4 w = __ldcs(&fb[64 + tid]);
            aB.x += w.x; aB.y += w.y; aB.z += w.z; aB.w += w.w;
        }
        fb += 75;
    }

    const float inv = 1.0f / (float)max(cnt, 1);
    float4* po = (float4*)(g_pooled + ((size_t)t * B_BATCH + b) * IN_DIM);
    po[tid] = make_float4(aA.x * inv, aA.y * inv, aA.z * inv, aA.w * inv);
    if (hasB)
        po[64 + tid] = make_float4(aB.x * inv, aB.y * inv, aB.z * inv, aB.w * inv);
}

// ---------------------------------------------------------------------------
// Kernel 2: per-type 2-layer MLP + transpose, f32x2 packed math.
// grid = (B/8, T) = (32, 27) = 864 blocks, 128 threads.
// Deep register prefetch of weights (12-/16-wide) to hide L2 latency.
// ---------------------------------------------------------------------------
#define ROWS 8
#define KG1  12   // GEMM1 k-group (300 = 25 * 12)
#define KG2  16   // GEMM2 j-group (128 = 8 * 16)

__global__ __launch_bounds__(128, 6)
void mlp_kernel(const float* __restrict__ W1,
                const float* __restrict__ b1,
                const float* __restrict__ W2,
                const float* __restrict__ b2,
                float* __restrict__ out) {
    const int t   = blockIdx.y;
    const int b0  = blockIdx.x * ROWS;
    const int tid = threadIdx.x;

    __shared__ float spt[IN_DIM * ROWS];  // [k][b] transposed, 9600 B
    __shared__ float ht[HID * ROWS];      // [j][b] transposed, 4096 B

    // ---- load pooled tile [8 x 300] transposed into spt[k][b] ----
    {
        const float* src = g_pooled + ((size_t)t * B_BATCH + b0) * IN_DIM;
        for (int idx = tid; idx < ROWS * IN_DIM; idx += 128) {
            int b = idx / IN_DIM;
            int k = idx - b * IN_DIM;
            spt[k * ROWS + b] = src[idx];
        }
    }
    __syncthreads();

    // ---- GEMM1: h[b][j] = relu(sum_k sp[b][k]*W1[k][j] + b1[j]), j = tid ----
    const int j = tid;
    ull acc[4];
    {
        ull binit = pack2(b1[t * HID + j]);
        #pragma unroll
        for (int p = 0; p < 4; ++p) acc[p] = binit;

        const float* w1p = W1 + (size_t)t * IN_DIM * HID + j;

        float wc[KG1], wn[KG1];
        #pragma unroll
        for (int i = 0; i < KG1; ++i) wc[i] = w1p[i * HID];

        for (int kg = 0; kg < IN_DIM / KG1; ++kg) {
            const int kbase = kg * KG1;
            if (kg + 1 < IN_DIM / KG1) {
                const float* wp2 = w1p + (kbase + KG1) * HID;
                #pragma unroll
                for (int i = 0; i < KG1; ++i) wn[i] = wp2[i * HID];
            }
            #pragma unroll
            for (int q = 0; q < KG1; ++q) {
                ull wp = pack2(wc[q]);
                const ulonglong2* sp = (const ulonglong2*)&spt[(kbase + q) * ROWS];
                ulonglong2 s0 = sp[0];
                ulonglong2 s1 = sp[1];
                acc[0] = fma2(wp, s0.x, acc[0]);
                acc[1] = fma2(wp, s0.y, acc[1]);
                acc[2] = fma2(wp, s1.x, acc[2]);
                acc[3] = fma2(wp, s1.y, acc[3]);
            }
            #pragma unroll
            for (int i = 0; i < KG1; ++i) wc[i] = wn[i];
        }
    }

    // relu + transposed store: ht[j][b]
    #pragma unroll
    for (int p = 0; p < 4; ++p) {
        float lo, hi;
        unpack2(acc[p], lo, hi);
        float2 v = make_float2(fmaxf(lo, 0.f), fmaxf(hi, 0.f));
        *(float2*)&ht[j * ROWS + 2 * p] = v;
    }
    __syncthreads();

    // ---- GEMM2: out[b][o] = sum_j h[b][j]*W2[j][o] + b2[o] ----
    const int o  = tid & 63;
    const int rh = tid >> 6;          // rows rh*4 .. rh*4+3 (2 pairs)
    ull acc2[2];
    {
        ull binit = pack2(b2[t * OUT_DIM + o]);
        acc2[0] = binit;
        acc2[1] = binit;

        const float* w2p = W2 + (size_t)t * HID * OUT_DIM + o;

        float wc[KG2], wn[KG2];
        #pragma unroll
        for (int i = 0; i < KG2; ++i) wc[i] = w2p[i * OUT_DIM];

        for (int jg = 0; jg < HID / KG2; ++jg) {
            const int jbase = jg * KG2;
            if (jg + 1 < HID / KG2) {
                const float* wp2 = w2p + (jbase + KG2) * OUT_DIM;
                #pragma unroll
                for (int i = 0; i < KG2; ++i) wn[i] = wp2[i * OUT_DIM];
            }
            #pragma unroll
            for (int q = 0; q < KG2; ++q) {
                ull wp = pack2(wc[q]);
                ulonglong2 h01 =
                    *(const ulonglong2*)&ht[(jbase + q) * ROWS + rh * 4];
                acc2[0] = fma2(wp, h01.x, acc2[0]);
                acc2[1] = fma2(wp, h01.y, acc2[1]);
            }
            #pragma unroll
            for (int i = 0; i < KG2; ++i) wc[i] = wn[i];
        }
    }

    // out layout: [B, T, OUT]
    #pragma unroll
    for (int p = 0; p < 2; ++p) {
        float lo, hi;
        unpack2(acc2[p], lo, hi);
        int r0 = b0 + rh * 4 + 2 * p;
        out[((size_t)r0 * T_TYPES + t) * OUT_DIM + o] = lo;
        out[((size_t)(r0 + 1) * T_TYPES + t) * OUT_DIM + o] = hi;
    }
}

// ---------------------------------------------------------------------------
extern "C" void kernel_launch(void* const* d_in, const int* in_sizes, int n_in,
                              void* d_out, int out_size) {
    const float* feat = (const float*)d_in[0];
    const int*   seg  = (const int*)d_in[1];
    const float* W1   = (const float*)d_in[2];
    const float* b1   = (const float*)d_in[3];
    const float* W2   = (const float*)d_in[4];
    const float* b2   = (const float*)d_in[5];
    float* out = (float*)d_out;

    dim3 pgrid(B_BATCH, T_TYPES);
    pool_kernel<<<pgrid, 64>>>(feat, seg);

    dim3 mgrid(B_BATCH / ROWS, T_TYPES);
    mlp_kernel<<<mgrid, 128>>>(W1, b1, W2, b2, out);
}